// round 16
// baseline (speedup 1.0000x reference)
#include <cuda_runtime.h>

#define N_VARS 2048
#define P      8
#define BATCH  4096
#define ROW    (N_VARS * P)      // 16384
#define COLS4  (N_VARS / 4)      // 512
#define THREADS 256

// 64 KB scratch: diag[lag*N_VARS + i] = weight[i, lag*N_VARS + i]
__device__ float g_diag[P * N_VARS];

__global__ __launch_bounds__(THREADS) void gather_diag_kernel(
    const float* __restrict__ weight)
{
    int idx = blockIdx.x * THREADS + threadIdx.x;  // 0 .. 16383
    int lag = idx >> 11;                           // / N_VARS
    int i   = idx & (N_VARS - 1);                  // % N_VARS
    g_diag[idx] = __ldg(&weight[(size_t)i * ROW + lag * N_VARS + i]);
}

__global__ __launch_bounds__(THREADS) void diag_linear_kernel(
    const float4* __restrict__ x,    // (4096, 16384) as float4
    float4*       __restrict__ out)  // (4096, 2048)  as float4
{
    int tid = blockIdx.x * THREADS + threadIdx.x;  // 0 .. BATCH*COLS4-1
    int b = tid / COLS4;
    int c = tid - b * COLS4;

    const float4* xrow  = x + (size_t)b * (ROW / 4);
    const float4* diag4 = reinterpret_cast<const float4*>(g_diag);

    float4 acc;
    acc.x = 0.f; acc.y = 0.f; acc.z = 0.f; acc.w = 0.f;

    #pragma unroll
    for (int lag = 0; lag < P; lag++) {
        float4 xv = __ldg(&xrow[lag * COLS4 + c]);
        float4 dv = __ldg(&diag4[lag * COLS4 + c]);
        acc.x = fmaf(xv.x, dv.x, acc.x);
        acc.y = fmaf(xv.y, dv.y, acc.y);
        acc.z = fmaf(xv.z, dv.z, acc.z);
        acc.w = fmaf(xv.w, dv.w, acc.w);
    }
    out[tid] = acc;
}

extern "C" void kernel_launch(void* const* d_in, const int* in_sizes, int n_in,
                              void* d_out, int out_size) {
    const float* x      = (const float*)d_in[0];   // (4096, 16384)
    const float* weight = (const float*)d_in[1];   // (2048, 16384)
    float* out          = (float*)d_out;           // (4096, 2048)

    // 1) gather diagonal: 64 blocks x 256 threads (measured-best shape)
    gather_diag_kernel<<<(P * N_VARS) / THREADS, THREADS>>>(weight);

    // 2) streaming diagonal contraction: 8192 x 256, 32 regs, ~89% occupancy,
    //    DRAM-roofline-bound at ~6.6 TB/s with traffic at the 288 MB floor.
    diag_linear_kernel<<<(BATCH * COLS4) / THREADS, THREADS>>>(
        reinterpret_cast<const float4*>(x),
        reinterpret_cast<float4*>(out));
}